// round 6
// baseline (speedup 1.0000x reference)
#include <cuda_runtime.h>
#include <math.h>

#define NH 16
#define ND 64
#define SEG_LEN 128

// Attention region: rows 0..255 -> 256*NH*ND floats = 262144 (1 MB)
#define ATTN_FLOATS (256 * NH * ND)
// Tail region to zero: (33554432 - 262144) floats * 4 B = 133169152 bytes
#define TAIL_BYTES ((size_t)(33554432 - ATTN_FLOATS) * 4)

#define THREADS 256
#define ATTN_CTAS 512   // 8 warps/CTA * 512 = 4096 warps = one per (q,h)

// ---------------------------------------------------------------------------
// Dilated attention over the two 128-query segments (writes rows 0..255 only).
// One warp per (seg*128+i, h); lanes own dims {lane, lane+32}; online softmax
// with monotone early-break under the causal mask (masked exps are exactly 0).
// ---------------------------------------------------------------------------
__global__ void attn_kernel(const float* __restrict__ q,
                            const float* __restrict__ k,
                            const float* __restrict__ v,
                            const int* __restrict__ is_causal_ptr,
                            float* __restrict__ out) {
    const int w    = blockIdx.x * (THREADS / 32) + (threadIdx.x >> 5); // 0..4095
    const int lane = threadIdx.x & 31;
    const int qh   = w & 255;          // seg*128 + i
    const int h    = w >> 8;           // 0..15
    const int seg  = qh >> 7;
    const int i    = qh & 127;
    const int seg_start = seg * SEG_LEN;
    const int step = SEG_LEN << seg;   // 128 (seg 0) or 256 (seg 1)
    const int qpos = seg_start + i;
    const int causal = is_causal_ptr[0];
    const float scale = 0.125f;        // 1/sqrt(64)

    const size_t qbase = ((size_t)qpos * NH + h) * ND;
    const float q0 = q[qbase + lane];
    const float q1 = q[qbase + lane + 32];

    float m = -INFINITY;
    float l = 0.f;
    float acc0 = 0.f, acc1 = 0.f;

    for (int j = 0; j < SEG_LEN; j++) {
        const int kpos = i + j * step;
        if (causal && kpos > qpos) break;  // monotone -> all later keys masked

        const size_t kb = ((size_t)kpos * NH + h) * ND;
        const float k0 = k[kb + lane];
        const float k1 = k[kb + lane + 32];
        const float v0 = v[kb + lane];
        const float v1 = v[kb + lane + 32];

        float s = q0 * k0 + q1 * k1;
        #pragma unroll
        for (int off = 16; off; off >>= 1)
            s += __shfl_xor_sync(0xffffffffu, s, off);
        s *= scale;

        const float mnew = fmaxf(m, s);
        const float corr = expf(m - mnew);   // 0 on first iter (m = -inf)
        const float p    = expf(s - mnew);
        l    = l * corr + p;
        acc0 = acc0 * corr + p * v0;
        acc1 = acc1 * corr + p * v1;
        m = mnew;
    }

    const float inv = 1.f / l;
    out[qbase + lane]      = acc0 * inv;
    out[qbase + lane + 32] = acc1 * inv;
}

// ---------------------------------------------------------------------------
// Launch: memset node (133 MB tail, driver-optimized pure-write stream) on the
// capture stream, attention kernel forked onto a side stream so it overlaps.
// Fresh stream/events per call (no statics; kernel_launch is called O(few)
// times, never during graph replay).
// ---------------------------------------------------------------------------
extern "C" void kernel_launch(void* const* d_in, const int* in_sizes, int n_in,
                              void* d_out, int out_size) {
    const float* q = (const float*)d_in[0];
    const float* k = (const float*)d_in[1];
    const float* v = (const float*)d_in[2];
    const int* is_causal = (const int*)d_in[3];
    float* out = (float*)d_out;
    (void)out_size; (void)n_in; (void)in_sizes;

    cudaStream_t side;
    cudaEvent_t ev_fork, ev_join;
    cudaStreamCreateWithFlags(&side, cudaStreamNonBlocking);
    cudaEventCreateWithFlags(&ev_fork, cudaEventDisableTiming);
    cudaEventCreateWithFlags(&ev_join, cudaEventDisableTiming);

    // Fork: side stream joins the capture after the fork event.
    cudaEventRecord(ev_fork, 0);
    cudaStreamWaitEvent(side, ev_fork, 0);

    // Attention (1 MB of rows 0..255) on the side stream.
    attn_kernel<<<ATTN_CTAS, THREADS, 0, side>>>(q, k, v, is_causal, out);

    // Bulk zero of the tail on the main (capture) stream.
    cudaMemsetAsync(out + ATTN_FLOATS, 0, TAIL_BYTES, 0);

    // Join: main stream waits for the attention kernel.
    cudaEventRecord(ev_join, side);
    cudaStreamWaitEvent(0, ev_join, 0);
}

// round 7
// speedup vs baseline: 1.0681x; 1.0681x over previous
#include <cuda_runtime.h>
#include <math.h>

#define NH 16
#define ND 64
#define SEG_LEN 128

// Attention region: rows 0..255 -> 256*NH*ND floats = 262144 (1 MB)
#define ATTN_FLOATS (256 * NH * ND)

#define THREADS 256
// 4096 (q,h) warps / 8 warps per block = 512 attention CTAs (placed FIRST,
// the measured-best arrangement: their latency chain hides under the store
// storm launched right behind them)
#define ATTN_CTAS 512
// zero region: 33554432 - 262144 = 33292288 floats = 4161536 x 32B v8-stores
// = 16256 CTAs x 256 threads, exactly one 256-bit store per thread
#define ZERO_CTAS 16256

// ---------------------------------------------------------------------------
// Fused kernel:
//   blocks [0, ATTN_CTAS)   -> dilated attention (writes rows 0..255)
//   blocks [ATTN_CTAS, ...) -> zero-fill, ONE st.global.v8.f32 per thread
// ---------------------------------------------------------------------------
__global__ void fused_kernel(const float* __restrict__ q,
                             const float* __restrict__ k,
                             const float* __restrict__ v,
                             const int* __restrict__ is_causal_ptr,
                             float* __restrict__ out) {
    if (blockIdx.x >= ATTN_CTAS) {
        // ------------------- zero-fill path (bulk of the grid) -------------
        const long long idx = (long long)(blockIdx.x - ATTN_CTAS) * THREADS
                            + threadIdx.x;
        float* dst = out + ATTN_FLOATS + idx * 8;   // 32-byte aligned
        asm volatile(
            "st.global.v8.f32 [%0], {%1, %1, %1, %1, %1, %1, %1, %1};"
            :: "l"(dst), "f"(0.0f) : "memory");
        return;
    }

    // ------------------- attention path (first 512 CTAs) -------------------
    const int w    = blockIdx.x * (THREADS / 32) + (threadIdx.x >> 5); // 0..4095
    const int lane = threadIdx.x & 31;
    const int qh   = w & 255;          // seg*128 + i
    const int h    = w >> 8;           // 0..15
    const int seg  = qh >> 7;
    const int i    = qh & 127;
    const int seg_start = seg * SEG_LEN;
    const int step = SEG_LEN << seg;   // 128 (seg 0) or 256 (seg 1)
    const int qpos = seg_start + i;
    const int causal = is_causal_ptr[0];
    const float scale = 0.125f;        // 1/sqrt(64)

    const size_t qbase = ((size_t)qpos * NH + h) * ND;
    const float q0 = q[qbase + lane];
    const float q1 = q[qbase + lane + 32];

    float m = -INFINITY;
    float l = 0.f;
    float acc0 = 0.f, acc1 = 0.f;

    for (int j = 0; j < SEG_LEN; j++) {
        const int kpos = i + j * step;
        if (causal && kpos > qpos) break;  // monotone -> all later keys masked

        const size_t kb = ((size_t)kpos * NH + h) * ND;
        const float k0 = k[kb + lane];
        const float k1 = k[kb + lane + 32];
        const float v0 = v[kb + lane];
        const float v1 = v[kb + lane + 32];

        float s = q0 * k0 + q1 * k1;
        #pragma unroll
        for (int off = 16; off; off >>= 1)
            s += __shfl_xor_sync(0xffffffffu, s, off);
        s *= scale;

        const float mnew = fmaxf(m, s);
        const float corr = expf(m - mnew);   // 0 on first iter (m = -inf)
        const float p    = expf(s - mnew);
        l    = l * corr + p;
        acc0 = acc0 * corr + p * v0;
        acc1 = acc1 * corr + p * v1;
        m = mnew;
    }

    const float inv = 1.f / l;
    out[qbase + lane]      = acc0 * inv;
    out[qbase + lane + 32] = acc1 * inv;
}

extern "C" void kernel_launch(void* const* d_in, const int* in_sizes, int n_in,
                              void* d_out, int out_size) {
    const float* q = (const float*)d_in[0];
    const float* k = (const float*)d_in[1];
    const float* v = (const float*)d_in[2];
    const int* is_causal = (const int*)d_in[3];
    float* out = (float*)d_out;

    (void)out_size; (void)n_in; (void)in_sizes;
    fused_kernel<<<ATTN_CTAS + ZERO_CTAS, THREADS>>>(q, k, v, is_causal, out);
}